// round 12
// baseline (speedup 1.0000x reference)
#include <cuda_runtime.h>

#define NN 50000
#define EE 1600000
#define FULL 0xffffffffu

typedef unsigned long long u64t;

__device__ __forceinline__ u64t pk(float lo, float hi) {
    u64t r; asm("mov.b64 %0,{%1,%2};" : "=l"(r) : "f"(lo), "f"(hi)); return r;
}
__device__ __forceinline__ void upk(u64t v, float& lo, float& hi) {
    asm("mov.b64 {%0,%1},%2;" : "=f"(lo), "=f"(hi) : "l"(v));
}
__device__ __forceinline__ u64t f2fma(u64t a, u64t b, u64t c) {
    u64t d; asm("fma.rn.f32x2 %0,%1,%2,%3;" : "=l"(d) : "l"(a), "l"(b), "l"(c)); return d;
}
__device__ __forceinline__ ulonglong2 ldcs2(const ulonglong2* p) {
    ulonglong2 r;
    asm("ld.global.cs.v2.u64 {%0,%1},[%2];" : "=l"(r.x), "=l"(r.y) : "l"(p));
    return r;
}

// ---------------- scratch ----------------------------------------------------
__device__ float g_q1[NN*128];
__device__ float g_k1[NN*128];
__device__ float g_v1[NN*128];
__device__ float g_h [NN*128];
__device__ float g_t1[NN*256];
__device__ float g_q2[NN*64];
__device__ float g_k2[NN*64];
__device__ float g_v2[NN*64];
__device__ float g_s2[NN*64];
__device__ float g_t2[NN*64];
__device__ int   g_cnt[NN];
__device__ int   g_rowptr[NN+1];
__device__ int   g_woff[NN];
__device__ int   g_bsum[64];
__device__ int2  g_edges[EE];

// ---------------- CSR build ---------------------------------------------------
__global__ void k_zero_cnt() {
    int i = blockIdx.x*blockDim.x + threadIdx.x;
    if (i < NN) g_cnt[i] = 0;
}
__global__ void k_hist(const int* __restrict__ dst) {
    int e = blockIdx.x*blockDim.x + threadIdx.x;
    if (e < EE) atomicAdd(&g_cnt[dst[e]], 1);
}
__global__ void k_scanA() {
    __shared__ int s[1024];
    int b = blockIdx.x;
    int i = b*1024 + threadIdx.x;
    int v = (i < NN) ? g_cnt[i] : 0;
    s[threadIdx.x] = v;
    __syncthreads();
    for (int off = 1; off < 1024; off <<= 1) {
        int t = (threadIdx.x >= off) ? s[threadIdx.x - off] : 0;
        __syncthreads();
        s[threadIdx.x] += t;
        __syncthreads();
    }
    if (i < NN) g_rowptr[i] = s[threadIdx.x] - v;
    if (threadIdx.x == 1023) g_bsum[b] = s[1023];
}
__global__ void k_scanB() {
    __shared__ int s[64];
    int t = threadIdx.x;
    int v = (t < 49) ? g_bsum[t] : 0;
    s[t] = v;
    __syncthreads();
    for (int off = 1; off < 64; off <<= 1) {
        int x = (t >= off) ? s[t - off] : 0;
        __syncthreads();
        s[t] += x;
        __syncthreads();
    }
    if (t < 49) g_bsum[t] = s[t] - v;
    if (t == 48) g_rowptr[NN] = s[48];
}
__global__ void k_scanC() {
    int i = blockIdx.x*blockDim.x + threadIdx.x;
    if (i < NN) {
        int r = g_rowptr[i] + g_bsum[i >> 10];
        g_rowptr[i] = r;
        g_woff[i] = r;
    }
}
__global__ void k_scatter(const int* __restrict__ src, const int* __restrict__ dst) {
    int e = blockIdx.x*blockDim.x + threadIdx.x;
    if (e < EE) {
        int d = dst[e];
        int p = atomicAdd(&g_woff[d], 1);
        g_edges[p] = make_int2(src[e], e);
    }
}

// ---------------- node linear layer 1 ----------------------------------------
__global__ void __launch_bounds__(256) k_node1(const float* __restrict__ x,
    const float* __restrict__ Wq, const float* __restrict__ bq,
    const float* __restrict__ Wk, const float* __restrict__ bk,
    const float* __restrict__ Wv, const float* __restrict__ bv,
    const float* __restrict__ Ws, const float* __restrict__ bs)
{
    const int CIN = 128, COUT = 128, BN = 64, KC = 16;
    int mat = blockIdx.y;
    const float* W = (mat==0)?Wq:((mat==1)?Wk:((mat==2)?Wv:Ws));
    const float* b = (mat==0)?bq:((mat==1)?bk:((mat==2)?bv:bs));
    float* o = (mat==0)?g_q1:((mat==1)?g_k1:((mat==2)?g_v1:g_h));
    int n0 = blockIdx.x * BN;
    int tid = threadIdx.x;
    int lane = tid & 31, ty = tid >> 5;

    __shared__ float xs[CIN][BN];
    __shared__ float ws2[KC][2*COUT];

    for (int i = tid; i < BN*CIN; i += 256) {
        int nn = i >> 7, c = i & 127;
        xs[c][nn] = (n0+nn < NN) ? x[(size_t)(n0+nn)*CIN + c] : 0.f;
    }

    u64t acc[4][4];
    #pragma unroll
    for (int c = 0; c < 4; c++) {
        float bc = b[lane + 32*c];
        u64t bp = pk(bc, bc);
        acc[0][c] = bp; acc[1][c] = bp; acc[2][c] = bp; acc[3][c] = bp;
    }

    for (int kc = 0; kc < CIN; kc += KC) {
        __syncthreads();
        for (int i = tid; i < KC*COUT; i += 256) {
            int kk = i >> 7, c = i & 127;
            float w = W[(size_t)(kc+kk)*COUT + c];
            *(float2*)&ws2[kk][2*c] = make_float2(w, w);
        }
        __syncthreads();
        #pragma unroll 4
        for (int kk = 0; kk < KC; kk++) {
            const u64t* xr = (const u64t*)&xs[kc+kk][ty*8];
            u64t x0 = xr[0], x1 = xr[1], x2 = xr[2], x3 = xr[3];
            const u64t* wr = (const u64t*)ws2[kk];
            u64t w0 = wr[lane], w1 = wr[lane+32], w2 = wr[lane+64], w3 = wr[lane+96];
            acc[0][0]=f2fma(x0,w0,acc[0][0]); acc[0][1]=f2fma(x0,w1,acc[0][1]);
            acc[0][2]=f2fma(x0,w2,acc[0][2]); acc[0][3]=f2fma(x0,w3,acc[0][3]);
            acc[1][0]=f2fma(x1,w0,acc[1][0]); acc[1][1]=f2fma(x1,w1,acc[1][1]);
            acc[1][2]=f2fma(x1,w2,acc[1][2]); acc[1][3]=f2fma(x1,w3,acc[1][3]);
            acc[2][0]=f2fma(x2,w0,acc[2][0]); acc[2][1]=f2fma(x2,w1,acc[2][1]);
            acc[2][2]=f2fma(x2,w2,acc[2][2]); acc[2][3]=f2fma(x2,w3,acc[2][3]);
            acc[3][0]=f2fma(x3,w0,acc[3][0]); acc[3][1]=f2fma(x3,w1,acc[3][1]);
            acc[3][2]=f2fma(x3,w2,acc[3][2]); acc[3][3]=f2fma(x3,w3,acc[3][3]);
        }
    }
    #pragma unroll
    for (int j = 0; j < 4; j++) {
        int r0 = n0 + ty*8 + 2*j, r1 = r0 + 1;
        #pragma unroll
        for (int c = 0; c < 4; c++) {
            float a0, a1; upk(acc[j][c], a0, a1);
            if (r0 < NN) o[(size_t)r0*COUT + lane + 32*c] = a0;
            if (r1 < NN) o[(size_t)r1*COUT + lane + 32*c] = a1;
        }
    }
}

__global__ void __launch_bounds__(256) k_node2(
    const float* __restrict__ Wq, const float* __restrict__ bq,
    const float* __restrict__ Wk, const float* __restrict__ bk,
    const float* __restrict__ Wv, const float* __restrict__ bv,
    const float* __restrict__ Ws, const float* __restrict__ bs)
{
    const int CIN = 128, COUT = 64, BN = 64, KC = 16;
    int mat = blockIdx.y;
    const float* W = (mat==0)?Wq:((mat==1)?Wk:((mat==2)?Wv:Ws));
    const float* b = (mat==0)?bq:((mat==1)?bk:((mat==2)?bv:bs));
    float* o = (mat==0)?g_q2:((mat==1)?g_k2:((mat==2)?g_v2:g_s2));
    int n0 = blockIdx.x * BN;
    int tid = threadIdx.x;
    int lane = tid & 31, ty = tid >> 5;

    __shared__ float xs[CIN][BN];
    __shared__ float ws2[KC][2*COUT];

    for (int i = tid; i < BN*CIN; i += 256) {
        int nn = i >> 7, c = i & 127;
        xs[c][nn] = (n0+nn < NN) ? g_h[(size_t)(n0+nn)*CIN + c] : 0.f;
    }

    u64t acc[4][2];
    #pragma unroll
    for (int c = 0; c < 2; c++) {
        float bc = b[lane + 32*c];
        u64t bp = pk(bc, bc);
        acc[0][c] = bp; acc[1][c] = bp; acc[2][c] = bp; acc[3][c] = bp;
    }

    for (int kc = 0; kc < CIN; kc += KC) {
        __syncthreads();
        for (int i = tid; i < KC*COUT; i += 256) {
            int kk = i >> 6, c = i & 63;
            float w = W[(size_t)(kc+kk)*COUT + c];
            *(float2*)&ws2[kk][2*c] = make_float2(w, w);
        }
        __syncthreads();
        #pragma unroll 4
        for (int kk = 0; kk < KC; kk++) {
            const u64t* xr = (const u64t*)&xs[kc+kk][ty*8];
            u64t x0 = xr[0], x1 = xr[1], x2 = xr[2], x3 = xr[3];
            const u64t* wr = (const u64t*)ws2[kk];
            u64t w0 = wr[lane], w1 = wr[lane+32];
            acc[0][0]=f2fma(x0,w0,acc[0][0]); acc[0][1]=f2fma(x0,w1,acc[0][1]);
            acc[1][0]=f2fma(x1,w0,acc[1][0]); acc[1][1]=f2fma(x1,w1,acc[1][1]);
            acc[2][0]=f2fma(x2,w0,acc[2][0]); acc[2][1]=f2fma(x2,w1,acc[2][1]);
            acc[3][0]=f2fma(x3,w0,acc[3][0]); acc[3][1]=f2fma(x3,w1,acc[3][1]);
        }
    }
    #pragma unroll
    for (int j = 0; j < 4; j++) {
        int r0 = n0 + ty*8 + 2*j, r1 = r0 + 1;
        #pragma unroll
        for (int c = 0; c < 2; c++) {
            float a0, a1; upk(acc[j][c], a0, a1);
            if (r0 < NN) o[(size_t)r0*COUT + lane + 32*c] = a0;
            if (r1 < NN) o[(size_t)r1*COUT + lane + 32*c] = a1;
        }
    }
}

// ---------------- t tables --------------------------------------------------
__global__ void k_t1(const float* __restrict__ We1) {
    int h = blockIdx.y;
    __shared__ float Wt[32][65];
    __shared__ float qsm[32][33];
    int tid = threadIdx.x;
    for (int i = tid; i < 64*32; i += 256) {
        int d = i >> 5, c = i & 31;
        Wt[c][d] = We1[(size_t)d*128 + h*32 + c];
    }
    int n0 = blockIdx.x * 32;
    for (int i = tid; i < 32*32; i += 256) {
        int nn = i >> 5, c = i & 31;
        qsm[nn][c] = (n0+nn < NN) ? g_q1[(size_t)(n0+nn)*128 + h*32 + c] : 0.f;
    }
    __syncthreads();
    int d = tid & 63, nb = tid >> 6;
    #pragma unroll
    for (int p = 0; p < 8; p++) {
        int nn = p*4 + nb;
        float acc = 0.f;
        #pragma unroll
        for (int c = 0; c < 32; c++) acc += qsm[nn][c] * Wt[c][d];
        if (n0+nn < NN) g_t1[(size_t)(n0+nn)*256 + h*64 + d] = acc;
    }
}

__global__ void k_t2(const float* __restrict__ We2) {
    __shared__ float Wt[64][65];
    __shared__ float qsm[32][65];
    int tid = threadIdx.x;
    for (int i = tid; i < 64*64; i += 256) {
        int d = i >> 6, c = i & 63;
        Wt[c][d] = We2[(size_t)d*64 + c];
    }
    int n0 = blockIdx.x * 32;
    for (int i = tid; i < 32*64; i += 256) {
        int nn = i >> 6, c = i & 63;
        qsm[nn][c] = (n0+nn < NN) ? g_q2[(size_t)(n0+nn)*64 + c] : 0.f;
    }
    __syncthreads();
    int d = tid & 63, nb = tid >> 6;
    #pragma unroll
    for (int p = 0; p < 8; p++) {
        int nn = p*4 + nb;
        float acc = 0.f;
        #pragma unroll
        for (int c = 0; c < 64; c++) acc += qsm[nn][c] * Wt[c][d];
        if (n0+nn < NN) g_t2[(size_t)(n0+nn)*64 + d] = acc;
    }
}

// ---------------- fused layer-1 attention: ef read ONCE, staged in smem ------
// 128 threads = 4 warps; warp per node. Per-warp smem: qs 128, ts 256 (reused
// as g for epilogue), aux 128, efs 1024 u64 (8KB).
__global__ void __launch_bounds__(128) k_fuse1(const float* __restrict__ ef,
                                               const float* __restrict__ We1) {
    int lane = threadIdx.x & 31;
    int wl   = threadIdx.x >> 5;
    int n    = blockIdx.x*4 + wl;
    __shared__ u64t  efsAll[4][1024];
    __shared__ float smemAll[4][512];
    u64t*  efs = efsAll[wl];
    float* qs  = smemAll[wl];        // 128
    float* ts  = qs + 128;           // 256 (pre-scaled; reused as g)
    float* aux = qs + 384;           // 128: w[32][4]
    if (n >= NN) return;

    const float inv_s = 0.1767766952966369f;   // 1/sqrt(32)
    {
        float4 q = ((const float4*)(g_q1 + (size_t)n*128))[lane];
        q.x*=inv_s; q.y*=inv_s; q.z*=inv_s; q.w*=inv_s;
        ((float4*)qs)[lane] = q;
        const float4* tsrc = (const float4*)(g_t1 + (size_t)n*256);
        float4 t0 = tsrc[lane], t1 = tsrc[lane+32];
        t0.x*=inv_s; t0.y*=inv_s; t0.z*=inv_s; t0.w*=inv_s;
        t1.x*=inv_s; t1.y*=inv_s; t1.z*=inv_s; t1.w*=inv_s;
        ((float4*)ts)[lane]    = t0;
        ((float4*)ts)[lane+32] = t1;
    }
    __syncwarp();

    int l8 = lane & 7, grp = lane >> 3;
    u64t accv0 = 0ull, accv1 = 0ull;     // v channels lane*4..+3 (head grp)
    u64t ag[4] = {0ull,0ull,0ull,0ull};  // g[h] channels lane*2..+1
    float den = 0.f;
    const u64t* qU = (const u64t*)qs;
    const u64t* tU = (const u64t*)ts;
    int qo = l8*2;

    int rs = g_rowptr[n], re = g_rowptr[n+1];
    for (int base = rs; base < re; base += 32) {
        int cnt = min(32, re - base);
        int2 se = make_int2(0, 0);
        if (lane < cnt) se = g_edges[base + lane];
        // ---- phase 1: scores, ef -> smem ----------------------------------
        #pragma unroll 2
        for (int sub = 0; sub < 8; sub++) {
            int el = sub*4 + grp;
            int esrc = __shfl_sync(FULL, se.x, el);
            int eeid = __shfl_sync(FULL, se.y, el);
            bool valid = el < cnt;
            const ulonglong2* kp = (const ulonglong2*)(g_k1 + (size_t)esrc*128);
            const ulonglong2* ep = (const ulonglong2*)(ef   + (size_t)eeid*64);
            ulonglong2 kv0 = kp[l8], kv1 = kp[8+l8], kv2 = kp[16+l8], kv3 = kp[24+l8];
            ulonglong2 ev0 = ldcs2(ep + l8), ev1 = ldcs2(ep + 8 + l8);
            // stash ef row in smem (u64 layout: row el, 32 u64)
            u64t* er = efs + el*32;
            er[l8*2]      = ev0.x;  er[l8*2+1]      = ev0.y;
            er[16 + l8*2] = ev1.x;  er[16 + l8*2+1] = ev1.y;

            u64t a0 = f2fma(kv0.x, qU[qo],    f2fma(kv0.y, qU[qo+1],    0ull));
            u64t a1 = f2fma(kv1.x, qU[16+qo], f2fma(kv1.y, qU[16+qo+1], 0ull));
            u64t a2 = f2fma(kv2.x, qU[32+qo], f2fma(kv2.y, qU[32+qo+1], 0ull));
            u64t a3 = f2fma(kv3.x, qU[48+qo], f2fma(kv3.y, qU[48+qo+1], 0ull));
            a0 = f2fma(ev0.x, tU[qo],     a0); a0 = f2fma(ev0.y, tU[qo+1],     a0);
            a0 = f2fma(ev1.x, tU[16+qo],  a0); a0 = f2fma(ev1.y, tU[16+qo+1],  a0);
            a1 = f2fma(ev0.x, tU[32+qo],  a1); a1 = f2fma(ev0.y, tU[32+qo+1],  a1);
            a1 = f2fma(ev1.x, tU[48+qo],  a1); a1 = f2fma(ev1.y, tU[48+qo+1],  a1);
            a2 = f2fma(ev0.x, tU[64+qo],  a2); a2 = f2fma(ev0.y, tU[64+qo+1],  a2);
            a2 = f2fma(ev1.x, tU[80+qo],  a2); a2 = f2fma(ev1.y, tU[80+qo+1],  a2);
            a3 = f2fma(ev0.x, tU[96+qo],  a3); a3 = f2fma(ev0.y, tU[96+qo+1],  a3);
            a3 = f2fma(ev1.x, tU[112+qo], a3); a3 = f2fma(ev1.y, tU[112+qo+1], a3);

            float s0,s1,s2,s3,t;
            upk(a0,s0,t); s0+=t;
            upk(a1,s1,t); s1+=t;
            upk(a2,s2,t); s2+=t;
            upk(a3,s3,t); s3+=t;
            #pragma unroll
            for (int o = 1; o <= 4; o <<= 1) {
                s0 += __shfl_xor_sync(FULL, s0, o);
                s1 += __shfl_xor_sync(FULL, s1, o);
                s2 += __shfl_xor_sync(FULL, s2, o);
                s3 += __shfl_xor_sync(FULL, s3, o);
            }
            if (l8 == 0) {
                float4 w4;
                w4.x = valid ? __expf(s0) : 0.f;
                w4.y = valid ? __expf(s1) : 0.f;
                w4.z = valid ? __expf(s2) : 0.f;
                w4.w = valid ? __expf(s3) : 0.f;
                *(float4*)(aux + el*4) = w4;
            }
        }
        __syncwarp();
        // ---- phase 2: accumulate (ef from smem, v from L2) ----------------
        #pragma unroll 2
        for (int e = 0; e < cnt; e++) {
            int esrc = __shfl_sync(FULL, se.x, e);
            const float* we = aux + e*4;
            float w0 = we[0], w1 = we[1], w2 = we[2], w3 = we[3];
            float wg = (grp==0)?w0:((grp==1)?w1:((grp==2)?w2:w3));
            den += wg;
            u64t wgP = pk(wg, wg);
            ulonglong2 vv = ((const ulonglong2*)(g_v1 + (size_t)esrc*128))[lane];
            accv0 = f2fma(wgP, vv.x, accv0);
            accv1 = f2fma(wgP, vv.y, accv1);
            u64t ev = efs[e*32 + lane];
            ag[0] = f2fma(pk(w0,w0), ev, ag[0]);
            ag[1] = f2fma(pk(w1,w1), ev, ag[1]);
            ag[2] = f2fma(pk(w2,w2), ev, ag[2]);
            ag[3] = f2fma(pk(w3,w3), ev, ag[3]);
        }
        __syncwarp();
    }

    // ---- epilogue (ts reused as g) ----------------------------------------
    __syncwarp();
    u64t* gU = (u64t*)ts;
    gU[0*32 + lane] = ag[0];
    gU[1*32 + lane] = ag[1];
    gU[2*32 + lane] = ag[2];
    gU[3*32 + lane] = ag[3];
    __syncwarp();

    float4 og = make_float4(0.f,0.f,0.f,0.f);
    const float* Wc = We1 + grp*32 + l8*4;
    const float* gh = ts + grp*64;
    #pragma unroll 8
    for (int d = 0; d < 64; d++) {
        float g = gh[d];
        float4 wr = *(const float4*)(Wc + (size_t)d*128);
        og.x += g*wr.x; og.y += g*wr.y; og.z += g*wr.z; og.w += g*wr.w;
    }
    float inv = (den > 0.f) ? (1.f/den) : 0.f;
    float4 av; upk(accv0, av.x, av.y); upk(accv1, av.z, av.w);
    float4 skip = *(const float4*)(g_h + (size_t)n*128 + lane*4);
    float4 o;
    o.x = fmaxf(fmaf(av.x + og.x, inv, skip.x), 0.f);
    o.y = fmaxf(fmaf(av.y + og.y, inv, skip.y), 0.f);
    o.z = fmaxf(fmaf(av.z + og.z, inv, skip.z), 0.f);
    o.w = fmaxf(fmaf(av.w + og.w, inv, skip.w), 0.f);
    *(float4*)(g_h + (size_t)n*128 + lane*4) = o;
}

// ---------------- fused layer-2 attention -------------------------------------
__global__ void __launch_bounds__(128) k_fuse2(const float* __restrict__ ef,
                                               const float* __restrict__ We2,
                                               float* __restrict__ out) {
    int lane = threadIdx.x & 31;
    int wl   = threadIdx.x >> 5;
    int n    = blockIdx.x*4 + wl;
    __shared__ u64t  efsAll[4][1024];
    __shared__ float smemAll[4][160];
    u64t*  efs = efsAll[wl];
    float* qs  = smemAll[wl];        // 64 (pre-scaled)
    float* ts  = qs + 64;            // 64 (pre-scaled; reused as g)
    float* aux = qs + 128;           // 32
    if (n >= NN) return;

    {
        float2 q = ((const float2*)(g_q2 + (size_t)n*64))[lane];
        q.x *= 0.125f; q.y *= 0.125f;
        ((float2*)qs)[lane] = q;
        float2 t = ((const float2*)(g_t2 + (size_t)n*64))[lane];
        t.x *= 0.125f; t.y *= 0.125f;
        ((float2*)ts)[lane] = t;
    }
    __syncwarp();

    int l8 = lane & 7, grp = lane >> 3;
    u64t accv = 0ull, ag = 0ull;
    float den = 0.f;
    const u64t* qU = (const u64t*)qs;
    const u64t* tU = (const u64t*)ts;
    int qo = l8*2;

    int rs = g_rowptr[n], re = g_rowptr[n+1];
    for (int base = rs; base < re; base += 32) {
        int cnt = min(32, re - base);
        int2 se = make_int2(0, 0);
        if (lane < cnt) se = g_edges[base + lane];
        // phase 1: scores, ef -> smem
        #pragma unroll 2
        for (int sub = 0; sub < 8; sub++) {
            int el = sub*4 + grp;
            int esrc = __shfl_sync(FULL, se.x, el);
            int eeid = __shfl_sync(FULL, se.y, el);
            bool valid = el < cnt;
            const ulonglong2* kp = (const ulonglong2*)(g_k2 + (size_t)esrc*64);
            const ulonglong2* ep = (const ulonglong2*)(ef   + (size_t)eeid*64);
            ulonglong2 kv0 = kp[l8], kv1 = kp[8+l8];
            ulonglong2 ev0 = ldcs2(ep + l8), ev1 = ldcs2(ep + 8 + l8);
            u64t* er = efs + el*32;
            er[l8*2]      = ev0.x;  er[l8*2+1]      = ev0.y;
            er[16 + l8*2] = ev1.x;  er[16 + l8*2+1] = ev1.y;

            u64t aP = f2fma(kv0.x, qU[qo],    f2fma(kv0.y, qU[qo+1], 0ull));
            aP = f2fma(kv1.x, qU[16+qo], aP); aP = f2fma(kv1.y, qU[16+qo+1], aP);
            aP = f2fma(ev0.x, tU[qo],    aP); aP = f2fma(ev0.y, tU[qo+1],    aP);
            aP = f2fma(ev1.x, tU[16+qo], aP); aP = f2fma(ev1.y, tU[16+qo+1], aP);
            float s, t; upk(aP, s, t); s += t;
            s += __shfl_xor_sync(FULL, s, 1);
            s += __shfl_xor_sync(FULL, s, 2);
            s += __shfl_xor_sync(FULL, s, 4);
            if (l8 == 0) aux[el] = valid ? __expf(s) : 0.f;
        }
        __syncwarp();
        // phase 2
        #pragma unroll 2
        for (int e = 0; e < cnt; e++) {
            int esrc = __shfl_sync(FULL, se.x, e);
            float w = aux[e];
            den += w;
            u64t wP = pk(w, w);
            u64t vv = ((const u64t*)(g_v2 + (size_t)esrc*64))[lane];
            accv = f2fma(wP, vv, accv);
            u64t ev = efs[e*32 + lane];
            ag = f2fma(wP, ev, ag);
        }
        __syncwarp();
    }

    __syncwarp();
    ((u64t*)ts)[lane] = ag;
    __syncwarp();

    float2 og = make_float2(0.f,0.f);
    const float* Wc = We2 + lane*2;
    #pragma unroll 8
    for (int d = 0; d < 64; d++) {
        float g = ts[d];
        float2 wr = *(const float2*)(Wc + (size_t)d*64);
        og.x += g*wr.x; og.y += g*wr.y;
    }
    float inv = (den > 0.f) ? (1.f/den) : 0.f;
    float2 av; upk(accv, av.x, av.y);
    float2 s2 = *(const float2*)(g_s2 + (size_t)n*64 + lane*2);
    float2 o;
    o.x = fmaf(av.x + og.x, inv, s2.x);
    o.y = fmaf(av.y + og.y, inv, s2.y);
    *(float2*)(out + (size_t)n*64 + lane*2) = o;
}

// ---------------- launch -------------------------------------------------------
extern "C" void kernel_launch(void* const* d_in, const int* in_sizes, int n_in,
                              void* d_out, int out_size)
{
    const float* x   = (const float*)d_in[0];
    const float* ef  = (const float*)d_in[1];
    const int*   ei  = (const int*)  d_in[2];
    const float *Wq1 = (const float*)d_in[3],  *bq1 = (const float*)d_in[4];
    const float *Wk1 = (const float*)d_in[5],  *bk1 = (const float*)d_in[6];
    const float *Wv1 = (const float*)d_in[7],  *bv1 = (const float*)d_in[8];
    const float *We1 = (const float*)d_in[9];
    const float *Ws1 = (const float*)d_in[10], *bs1 = (const float*)d_in[11];
    const float *Wq2 = (const float*)d_in[12], *bq2 = (const float*)d_in[13];
    const float *Wk2 = (const float*)d_in[14], *bk2 = (const float*)d_in[15];
    const float *Wv2 = (const float*)d_in[16], *bv2 = (const float*)d_in[17];
    const float *We2 = (const float*)d_in[18];
    const float *Ws2 = (const float*)d_in[19], *bs2 = (const float*)d_in[20];
    float* out = (float*)d_out;

    const int* srcp = ei;
    const int* dstp = ei + EE;

    // CSR build
    k_zero_cnt<<<(NN+255)/256, 256>>>();
    k_hist    <<<(EE+255)/256, 256>>>(dstp);
    k_scanA   <<<49, 1024>>>();
    k_scanB   <<<1, 64>>>();
    k_scanC   <<<(NN+255)/256, 256>>>();
    k_scatter <<<(EE+255)/256, 256>>>(srcp, dstp);

    // layer 1
    dim3 g1((NN+63)/64, 4);
    k_node1<<<g1, 256>>>(x, Wq1,bq1, Wk1,bk1, Wv1,bv1, Ws1,bs1);
    dim3 gt1((NN+31)/32, 4);
    k_t1   <<<gt1, 256>>>(We1);
    k_fuse1<<<(NN+3)/4, 128>>>(ef, We1);

    // layer 2
    dim3 g2((NN+63)/64, 4);
    k_node2<<<g2, 256>>>(Wq2,bq2, Wk2,bk2, Wv2,bv2, Ws2,bs2);
    k_t2   <<<(NN+31)/32, 256>>>(We2);
    k_fuse2<<<(NN+3)/4, 128>>>(ef, We2, out);
}

// round 13
// speedup vs baseline: 1.0635x; 1.0635x over previous
#include <cuda_runtime.h>

#define NN 50000
#define EE 1600000
#define FULL 0xffffffffu

typedef unsigned long long u64t;

__device__ __forceinline__ u64t pk(float lo, float hi) {
    u64t r; asm("mov.b64 %0,{%1,%2};" : "=l"(r) : "f"(lo), "f"(hi)); return r;
}
__device__ __forceinline__ void upk(u64t v, float& lo, float& hi) {
    asm("mov.b64 {%0,%1},%2;" : "=f"(lo), "=f"(hi) : "l"(v));
}
__device__ __forceinline__ u64t f2fma(u64t a, u64t b, u64t c) {
    u64t d; asm("fma.rn.f32x2 %0,%1,%2,%3;" : "=l"(d) : "l"(a), "l"(b), "l"(c)); return d;
}
__device__ __forceinline__ ulonglong2 ldcs2(const ulonglong2* p) {
    ulonglong2 r;
    asm("ld.global.cs.v2.u64 {%0,%1},[%2];" : "=l"(r.x), "=l"(r.y) : "l"(p));
    return r;
}
__device__ __forceinline__ u64t ldcs1(const u64t* p) {
    u64t r; asm("ld.global.cs.u64 %0,[%1];" : "=l"(r) : "l"(p)); return r;
}

// ---------------- scratch ----------------------------------------------------
__device__ float g_q1[NN*128];
__device__ float g_k1[NN*128];
__device__ float g_v1[NN*128];
__device__ float g_h [NN*128];
__device__ float g_t1[NN*256];
__device__ float g_q2[NN*64];
__device__ float g_k2[NN*64];
__device__ float g_v2[NN*64];
__device__ float g_s2[NN*64];
__device__ float g_t2[NN*64];
__device__ float g_w [EE*4];
__device__ int   g_cnt[NN];
__device__ int   g_rowptr[NN+1];
__device__ int   g_woff[NN];
__device__ int   g_bsum[64];
__device__ int2  g_edges[EE];
__device__ int   g_edst[EE];

// ---------------- CSR build ---------------------------------------------------
__global__ void k_zero_cnt() {
    int i = blockIdx.x*blockDim.x + threadIdx.x;
    if (i < NN) g_cnt[i] = 0;
}
__global__ void k_hist(const int* __restrict__ dst) {
    int e = blockIdx.x*blockDim.x + threadIdx.x;
    if (e < EE) atomicAdd(&g_cnt[dst[e]], 1);
}
__global__ void k_scanA() {
    __shared__ int s[1024];
    int b = blockIdx.x;
    int i = b*1024 + threadIdx.x;
    int v = (i < NN) ? g_cnt[i] : 0;
    s[threadIdx.x] = v;
    __syncthreads();
    for (int off = 1; off < 1024; off <<= 1) {
        int t = (threadIdx.x >= off) ? s[threadIdx.x - off] : 0;
        __syncthreads();
        s[threadIdx.x] += t;
        __syncthreads();
    }
    if (i < NN) g_rowptr[i] = s[threadIdx.x] - v;
    if (threadIdx.x == 1023) g_bsum[b] = s[1023];
}
__global__ void k_scanB() {
    __shared__ int s[64];
    int t = threadIdx.x;
    int v = (t < 49) ? g_bsum[t] : 0;
    s[t] = v;
    __syncthreads();
    for (int off = 1; off < 64; off <<= 1) {
        int x = (t >= off) ? s[t - off] : 0;
        __syncthreads();
        s[t] += x;
        __syncthreads();
    }
    if (t < 49) g_bsum[t] = s[t] - v;
    if (t == 48) g_rowptr[NN] = s[48];
}
__global__ void k_scanC() {
    int i = blockIdx.x*blockDim.x + threadIdx.x;
    if (i < NN) {
        int r = g_rowptr[i] + g_bsum[i >> 10];
        g_rowptr[i] = r;
        g_woff[i] = r;
    }
}
__global__ void k_scatter(const int* __restrict__ src, const int* __restrict__ dst) {
    int e = blockIdx.x*blockDim.x + threadIdx.x;
    if (e < EE) {
        int d = dst[e];
        int p = atomicAdd(&g_woff[d], 1);
        g_edges[p] = make_int2(src[e], e);
        g_edst[p] = d;
    }
}

// ---------------- node linear layer 1 (R8) -----------------------------------
__global__ void __launch_bounds__(256) k_node1(const float* __restrict__ x,
    const float* __restrict__ Wq, const float* __restrict__ bq,
    const float* __restrict__ Wk, const float* __restrict__ bk,
    const float* __restrict__ Wv, const float* __restrict__ bv,
    const float* __restrict__ Ws, const float* __restrict__ bs)
{
    const int CIN = 128, COUT = 128, BN = 64, KC = 16;
    int mat = blockIdx.y;
    const float* W = (mat==0)?Wq:((mat==1)?Wk:((mat==2)?Wv:Ws));
    const float* b = (mat==0)?bq:((mat==1)?bk:((mat==2)?bv:bs));
    float* o = (mat==0)?g_q1:((mat==1)?g_k1:((mat==2)?g_v1:g_h));
    int n0 = blockIdx.x * BN;
    int tid = threadIdx.x;
    int lane = tid & 31, ty = tid >> 5;

    __shared__ float xs[CIN][BN];
    __shared__ float ws2[KC][2*COUT];

    for (int i = tid; i < BN*CIN; i += 256) {
        int nn = i >> 7, c = i & 127;
        xs[c][nn] = (n0+nn < NN) ? x[(size_t)(n0+nn)*CIN + c] : 0.f;
    }

    u64t acc[4][4];
    #pragma unroll
    for (int c = 0; c < 4; c++) {
        float bc = b[lane + 32*c];
        u64t bp = pk(bc, bc);
        acc[0][c] = bp; acc[1][c] = bp; acc[2][c] = bp; acc[3][c] = bp;
    }

    for (int kc = 0; kc < CIN; kc += KC) {
        __syncthreads();
        for (int i = tid; i < KC*COUT; i += 256) {
            int kk = i >> 7, c = i & 127;
            float w = W[(size_t)(kc+kk)*COUT + c];
            *(float2*)&ws2[kk][2*c] = make_float2(w, w);
        }
        __syncthreads();
        #pragma unroll 4
        for (int kk = 0; kk < KC; kk++) {
            const u64t* xr = (const u64t*)&xs[kc+kk][ty*8];
            u64t x0 = xr[0], x1 = xr[1], x2 = xr[2], x3 = xr[3];
            const u64t* wr = (const u64t*)ws2[kk];
            u64t w0 = wr[lane], w1 = wr[lane+32], w2 = wr[lane+64], w3 = wr[lane+96];
            acc[0][0]=f2fma(x0,w0,acc[0][0]); acc[0][1]=f2fma(x0,w1,acc[0][1]);
            acc[0][2]=f2fma(x0,w2,acc[0][2]); acc[0][3]=f2fma(x0,w3,acc[0][3]);
            acc[1][0]=f2fma(x1,w0,acc[1][0]); acc[1][1]=f2fma(x1,w1,acc[1][1]);
            acc[1][2]=f2fma(x1,w2,acc[1][2]); acc[1][3]=f2fma(x1,w3,acc[1][3]);
            acc[2][0]=f2fma(x2,w0,acc[2][0]); acc[2][1]=f2fma(x2,w1,acc[2][1]);
            acc[2][2]=f2fma(x2,w2,acc[2][2]); acc[2][3]=f2fma(x2,w3,acc[2][3]);
            acc[3][0]=f2fma(x3,w0,acc[3][0]); acc[3][1]=f2fma(x3,w1,acc[3][1]);
            acc[3][2]=f2fma(x3,w2,acc[3][2]); acc[3][3]=f2fma(x3,w3,acc[3][3]);
        }
    }
    #pragma unroll
    for (int j = 0; j < 4; j++) {
        int r0 = n0 + ty*8 + 2*j, r1 = r0 + 1;
        #pragma unroll
        for (int c = 0; c < 4; c++) {
            float a0, a1; upk(acc[j][c], a0, a1);
            if (r0 < NN) o[(size_t)r0*COUT + lane + 32*c] = a0;
            if (r1 < NN) o[(size_t)r1*COUT + lane + 32*c] = a1;
        }
    }
}

__global__ void __launch_bounds__(256) k_node2(
    const float* __restrict__ Wq, const float* __restrict__ bq,
    const float* __restrict__ Wk, const float* __restrict__ bk,
    const float* __restrict__ Wv, const float* __restrict__ bv,
    const float* __restrict__ Ws, const float* __restrict__ bs)
{
    const int CIN = 128, COUT = 64, BN = 64, KC = 16;
    int mat = blockIdx.y;
    const float* W = (mat==0)?Wq:((mat==1)?Wk:((mat==2)?Wv:Ws));
    const float* b = (mat==0)?bq:((mat==1)?bk:((mat==2)?bv:bs));
    float* o = (mat==0)?g_q2:((mat==1)?g_k2:((mat==2)?g_v2:g_s2));
    int n0 = blockIdx.x * BN;
    int tid = threadIdx.x;
    int lane = tid & 31, ty = tid >> 5;

    __shared__ float xs[CIN][BN];
    __shared__ float ws2[KC][2*COUT];

    for (int i = tid; i < BN*CIN; i += 256) {
        int nn = i >> 7, c = i & 127;
        xs[c][nn] = (n0+nn < NN) ? g_h[(size_t)(n0+nn)*CIN + c] : 0.f;
    }

    u64t acc[4][2];
    #pragma unroll
    for (int c = 0; c < 2; c++) {
        float bc = b[lane + 32*c];
        u64t bp = pk(bc, bc);
        acc[0][c] = bp; acc[1][c] = bp; acc[2][c] = bp; acc[3][c] = bp;
    }

    for (int kc = 0; kc < CIN; kc += KC) {
        __syncthreads();
        for (int i = tid; i < KC*COUT; i += 256) {
            int kk = i >> 6, c = i & 63;
            float w = W[(size_t)(kc+kk)*COUT + c];
            *(float2*)&ws2[kk][2*c] = make_float2(w, w);
        }
        __syncthreads();
        #pragma unroll 4
        for (int kk = 0; kk < KC; kk++) {
            const u64t* xr = (const u64t*)&xs[kc+kk][ty*8];
            u64t x0 = xr[0], x1 = xr[1], x2 = xr[2], x3 = xr[3];
            const u64t* wr = (const u64t*)ws2[kk];
            u64t w0 = wr[lane], w1 = wr[lane+32];
            acc[0][0]=f2fma(x0,w0,acc[0][0]); acc[0][1]=f2fma(x0,w1,acc[0][1]);
            acc[1][0]=f2fma(x1,w0,acc[1][0]); acc[1][1]=f2fma(x1,w1,acc[1][1]);
            acc[2][0]=f2fma(x2,w0,acc[2][0]); acc[2][1]=f2fma(x2,w1,acc[2][1]);
            acc[3][0]=f2fma(x3,w0,acc[3][0]); acc[3][1]=f2fma(x3,w1,acc[3][1]);
        }
    }
    #pragma unroll
    for (int j = 0; j < 4; j++) {
        int r0 = n0 + ty*8 + 2*j, r1 = r0 + 1;
        #pragma unroll
        for (int c = 0; c < 2; c++) {
            float a0, a1; upk(acc[j][c], a0, a1);
            if (r0 < NN) o[(size_t)r0*COUT + lane + 32*c] = a0;
            if (r1 < NN) o[(size_t)r1*COUT + lane + 32*c] = a1;
        }
    }
}

// ---------------- t tables --------------------------------------------------
__global__ void k_t1(const float* __restrict__ We1) {
    int h = blockIdx.y;
    __shared__ float Wt[32][65];
    __shared__ float qsm[32][33];
    int tid = threadIdx.x;
    for (int i = tid; i < 64*32; i += 256) {
        int d = i >> 5, c = i & 31;
        Wt[c][d] = We1[(size_t)d*128 + h*32 + c];
    }
    int n0 = blockIdx.x * 32;
    for (int i = tid; i < 32*32; i += 256) {
        int nn = i >> 5, c = i & 31;
        qsm[nn][c] = (n0+nn < NN) ? g_q1[(size_t)(n0+nn)*128 + h*32 + c] : 0.f;
    }
    __syncthreads();
    int d = tid & 63, nb = tid >> 6;
    #pragma unroll
    for (int p = 0; p < 8; p++) {
        int nn = p*4 + nb;
        float acc = 0.f;
        #pragma unroll
        for (int c = 0; c < 32; c++) acc += qsm[nn][c] * Wt[c][d];
        if (n0+nn < NN) g_t1[(size_t)(n0+nn)*256 + h*64 + d] = acc;
    }
}

__global__ void k_t2(const float* __restrict__ We2) {
    __shared__ float Wt[64][65];
    __shared__ float qsm[32][65];
    int tid = threadIdx.x;
    for (int i = tid; i < 64*64; i += 256) {
        int d = i >> 6, c = i & 63;
        Wt[c][d] = We2[(size_t)d*64 + c];
    }
    int n0 = blockIdx.x * 32;
    for (int i = tid; i < 32*64; i += 256) {
        int nn = i >> 6, c = i & 63;
        qsm[nn][c] = (n0+nn < NN) ? g_q2[(size_t)(n0+nn)*64 + c] : 0.f;
    }
    __syncthreads();
    int d = tid & 63, nb = tid >> 6;
    #pragma unroll
    for (int p = 0; p < 8; p++) {
        int nn = p*4 + nb;
        float acc = 0.f;
        #pragma unroll
        for (int c = 0; c < 64; c++) acc += qsm[nn][c] * Wt[c][d];
        if (n0+nn < NN) g_t2[(size_t)(n0+nn)*64 + d] = acc;
    }
}

// ---------------- layer-1 scores: edge-parallel, 2 edges per 8-lane group ----
__global__ void __launch_bounds__(128) k_score1(const float* __restrict__ ef) {
    int tid  = threadIdx.x;
    int lane = tid & 31;
    int l8   = lane & 7;
    int i0   = blockIdx.x*32 + (tid >> 3)*2;   // EE % 32 == 0
    if (i0 >= EE) return;

    int2 seA = g_edges[i0],   seB = g_edges[i0+1];
    int  dnA = g_edst[i0],    dnB = g_edst[i0+1];

    const ulonglong2* kpA = (const ulonglong2*)(g_k1 + (size_t)seA.x*128);
    const ulonglong2* kpB = (const ulonglong2*)(g_k1 + (size_t)seB.x*128);
    const ulonglong2* qpA = (const ulonglong2*)(g_q1 + (size_t)dnA*128);
    const ulonglong2* qpB = (const ulonglong2*)(g_q1 + (size_t)dnB*128);
    const ulonglong2* epA = (const ulonglong2*)(ef   + (size_t)seA.y*64);
    const ulonglong2* epB = (const ulonglong2*)(ef   + (size_t)seB.y*64);
    const ulonglong2* tpA = (const ulonglong2*)(g_t1 + (size_t)dnA*256);
    const ulonglong2* tpB = (const ulonglong2*)(g_t1 + (size_t)dnB*256);

    // issue both edges' streaming loads up front (MLP x2)
    ulonglong2 evA0 = ldcs2(epA + l8), evA1 = ldcs2(epA + 8 + l8);
    ulonglong2 evB0 = ldcs2(epB + l8), evB1 = ldcs2(epB + 8 + l8);

    u64t aA[4], aB[4];
    #pragma unroll
    for (int h = 0; h < 4; h++) {
        ulonglong2 kvA = kpA[h*8 + l8], qvA = qpA[h*8 + l8];
        ulonglong2 kvB = kpB[h*8 + l8], qvB = qpB[h*8 + l8];
        aA[h] = f2fma(kvA.x, qvA.x, 0ull); aA[h] = f2fma(kvA.y, qvA.y, aA[h]);
        aB[h] = f2fma(kvB.x, qvB.x, 0ull); aB[h] = f2fma(kvB.y, qvB.y, aB[h]);
    }
    #pragma unroll
    for (int h = 0; h < 4; h++) {
        ulonglong2 tvA0 = tpA[h*16 + l8], tvA1 = tpA[h*16 + 8 + l8];
        ulonglong2 tvB0 = tpB[h*16 + l8], tvB1 = tpB[h*16 + 8 + l8];
        aA[h] = f2fma(evA0.x, tvA0.x, aA[h]); aA[h] = f2fma(evA0.y, tvA0.y, aA[h]);
        aA[h] = f2fma(evA1.x, tvA1.x, aA[h]); aA[h] = f2fma(evA1.y, tvA1.y, aA[h]);
        aB[h] = f2fma(evB0.x, tvB0.x, aB[h]); aB[h] = f2fma(evB0.y, tvB0.y, aB[h]);
        aB[h] = f2fma(evB1.x, tvB1.x, aB[h]); aB[h] = f2fma(evB1.y, tvB1.y, aB[h]);
    }
    float sA[4], sB[4], t;
    #pragma unroll
    for (int h = 0; h < 4; h++) {
        upk(aA[h], sA[h], t); sA[h] += t;
        upk(aB[h], sB[h], t); sB[h] += t;
    }
    #pragma unroll
    for (int o = 1; o <= 4; o <<= 1) {
        #pragma unroll
        for (int h = 0; h < 4; h++) {
            sA[h] += __shfl_xor_sync(FULL, sA[h], o);
            sB[h] += __shfl_xor_sync(FULL, sB[h], o);
        }
    }
    if (l8 == 0) {
        const float inv_s = 0.1767766952966369f;   // 1/sqrt(32)
        float4 wA, wB;
        wA.x = __expf(sA[0]*inv_s); wA.y = __expf(sA[1]*inv_s);
        wA.z = __expf(sA[2]*inv_s); wA.w = __expf(sA[3]*inv_s);
        wB.x = __expf(sB[0]*inv_s); wB.y = __expf(sB[1]*inv_s);
        wB.z = __expf(sB[2]*inv_s); wB.w = __expf(sB[3]*inv_s);
        *(float4*)(g_w + (size_t)i0*4)     = wA;
        *(float4*)(g_w + (size_t)(i0+1)*4) = wB;
    }
}

// ---------------- layer-1 aggregate (R8) --------------------------------------
__global__ void __launch_bounds__(256) k_agg1(const float* __restrict__ ef,
                                              const float* __restrict__ We1) {
    int lane = threadIdx.x & 31;
    int wl   = threadIdx.x >> 5;
    int n    = blockIdx.x*8 + wl;
    __shared__ float smemAll[8*384];
    float* aux = smemAll + wl*384;
    float* gsm = aux + 128;
    if (n >= NN) return;

    int l8 = lane & 7, grp = lane >> 3;
    u64t accv0 = 0ull, accv1 = 0ull;
    u64t ag[4] = {0ull,0ull,0ull,0ull};
    float den = 0.f;

    int rs = g_rowptr[n], re = g_rowptr[n+1];
    for (int base = rs; base < re; base += 32) {
        int cnt = min(32, re - base);
        int2 se = make_int2(0, 0);
        if (lane < cnt) {
            se = g_edges[base + lane];
            *(float4*)(aux + lane*4) = *(const float4*)(g_w + (size_t)(base+lane)*4);
        }
        __syncwarp();
        #pragma unroll 2
        for (int e = 0; e < cnt; e++) {
            int esrc = __shfl_sync(FULL, se.x, e);
            int eeid = __shfl_sync(FULL, se.y, e);
            const float* we = aux + e*4;
            float w0 = we[0], w1 = we[1], w2 = we[2], w3 = we[3];
            float wg = (grp==0)?w0:((grp==1)?w1:((grp==2)?w2:w3));
            den += wg;
            u64t wgP = pk(wg, wg);
            ulonglong2 vv = ((const ulonglong2*)(g_v1 + (size_t)esrc*128))[lane];
            accv0 = f2fma(wgP, vv.x, accv0);
            accv1 = f2fma(wgP, vv.y, accv1);
            u64t ev = ldcs1((const u64t*)(ef + (size_t)eeid*64) + lane);
            ag[0] = f2fma(pk(w0,w0), ev, ag[0]);
            ag[1] = f2fma(pk(w1,w1), ev, ag[1]);
            ag[2] = f2fma(pk(w2,w2), ev, ag[2]);
            ag[3] = f2fma(pk(w3,w3), ev, ag[3]);
        }
        __syncwarp();
    }

    u64t* gU = (u64t*)gsm;
    gU[0*32 + lane] = ag[0];
    gU[1*32 + lane] = ag[1];
    gU[2*32 + lane] = ag[2];
    gU[3*32 + lane] = ag[3];
    __syncwarp();

    float4 og = make_float4(0.f,0.f,0.f,0.f);
    const float* Wc = We1 + grp*32 + l8*4;
    const float* gh = gsm + grp*64;
    #pragma unroll 8
    for (int d = 0; d < 64; d++) {
        float g = gh[d];
        float4 wr = *(const float4*)(Wc + (size_t)d*128);
        og.x += g*wr.x; og.y += g*wr.y; og.z += g*wr.z; og.w += g*wr.w;
    }
    float inv = (den > 0.f) ? (1.f/den) : 0.f;
    float4 av; upk(accv0, av.x, av.y); upk(accv1, av.z, av.w);
    float4 skip = *(const float4*)(g_h + (size_t)n*128 + lane*4);
    float4 o;
    o.x = fmaxf(fmaf(av.x + og.x, inv, skip.x), 0.f);
    o.y = fmaxf(fmaf(av.y + og.y, inv, skip.y), 0.f);
    o.z = fmaxf(fmaf(av.z + og.z, inv, skip.z), 0.f);
    o.w = fmaxf(fmaf(av.w + og.w, inv, skip.w), 0.f);
    *(float4*)(g_h + (size_t)n*128 + lane*4) = o;
}

// ---------------- layer-2 scores: edge-parallel, 2 edges per group ------------
__global__ void __launch_bounds__(128) k_score2(const float* __restrict__ ef) {
    int tid  = threadIdx.x;
    int lane = tid & 31;
    int l8   = lane & 7;
    int i0   = blockIdx.x*32 + (tid >> 3)*2;
    if (i0 >= EE) return;

    int2 seA = g_edges[i0],   seB = g_edges[i0+1];
    int  dnA = g_edst[i0],    dnB = g_edst[i0+1];

    const ulonglong2* kpA = (const ulonglong2*)(g_k2 + (size_t)seA.x*64);
    const ulonglong2* kpB = (const ulonglong2*)(g_k2 + (size_t)seB.x*64);
    const ulonglong2* qpA = (const ulonglong2*)(g_q2 + (size_t)dnA*64);
    const ulonglong2* qpB = (const ulonglong2*)(g_q2 + (size_t)dnB*64);
    const ulonglong2* epA = (const ulonglong2*)(ef   + (size_t)seA.y*64);
    const ulonglong2* epB = (const ulonglong2*)(ef   + (size_t)seB.y*64);
    const ulonglong2* tpA = (const ulonglong2*)(g_t2 + (size_t)dnA*64);
    const ulonglong2* tpB = (const ulonglong2*)(g_t2 + (size_t)dnB*64);

    ulonglong2 evA0 = ldcs2(epA + l8), evA1 = ldcs2(epA + 8 + l8);
    ulonglong2 evB0 = ldcs2(epB + l8), evB1 = ldcs2(epB + 8 + l8);
    ulonglong2 kvA0 = kpA[l8], kvA1 = kpA[8+l8];
    ulonglong2 kvB0 = kpB[l8], kvB1 = kpB[8+l8];
    ulonglong2 qvA0 = qpA[l8], qvA1 = qpA[8+l8];
    ulonglong2 qvB0 = qpB[l8], qvB1 = qpB[8+l8];
    ulonglong2 tvA0 = tpA[l8], tvA1 = tpA[8+l8];
    ulonglong2 tvB0 = tpB[l8], tvB1 = tpB[8+l8];

    u64t aA = f2fma(kvA0.x, qvA0.x, 0ull);
    aA = f2fma(kvA0.y, qvA0.y, aA);
    aA = f2fma(kvA1.x, qvA1.x, aA);
    aA = f2fma(kvA1.y, qvA1.y, aA);
    aA = f2fma(evA0.x, tvA0.x, aA);
    aA = f2fma(evA0.y, tvA0.y, aA);
    aA = f2fma(evA1.x, tvA1.x, aA);
    aA = f2fma(evA1.y, tvA1.y, aA);
    u64t aB = f2fma(kvB0.x, qvB0.x, 0ull);
    aB = f2fma(kvB0.y, qvB0.y, aB);
    aB = f2fma(kvB1.x, qvB1.x, aB);
    aB = f2fma(kvB1.y, qvB1.y, aB);
    aB = f2fma(evB0.x, tvB0.x, aB);
    aB = f2fma(evB0.y, tvB0.y, aB);
    aB = f2fma(evB1.x, tvB1.x, aB);
    aB = f2fma(evB1.y, tvB1.y, aB);

    float sA, sB, t;
    upk(aA, sA, t); sA += t;
    upk(aB, sB, t); sB += t;
    #pragma unroll
    for (int o = 1; o <= 4; o <<= 1) {
        sA += __shfl_xor_sync(FULL, sA, o);
        sB += __shfl_xor_sync(FULL, sB, o);
    }
    if (l8 == 0) {
        g_w[i0]   = __expf(sA*0.125f);
        g_w[i0+1] = __expf(sB*0.125f);
    }
}

// ---------------- layer-2 aggregate (R8) ---------------------------------------
__global__ void __launch_bounds__(256) k_agg2(const float* __restrict__ ef,
                                              const float* __restrict__ We2,
                                              float* __restrict__ out) {
    int lane = threadIdx.x & 31;
    int wl   = threadIdx.x >> 5;
    int n    = blockIdx.x*8 + wl;
    __shared__ float smemAll[8*96];
    float* aux = smemAll + wl*96;
    float* gsm = aux + 32;
    if (n >= NN) return;

    u64t accv = 0ull;
    u64t ag   = 0ull;
    float den = 0.f;
    int rs = g_rowptr[n], re = g_rowptr[n+1];

    for (int base = rs; base < re; base += 32) {
        int cnt = min(32, re - base);
        int2 se = make_int2(0, 0);
        if (lane < cnt) {
            se = g_edges[base + lane];
            aux[lane] = g_w[base + lane];
        }
        __syncwarp();
        #pragma unroll 2
        for (int e = 0; e < cnt; e++) {
            int esrc = __shfl_sync(FULL, se.x, e);
            int eeid = __shfl_sync(FULL, se.y, e);
            float w = aux[e];
            den += w;
            u64t wP = pk(w, w);
            u64t vv = ((const u64t*)(g_v2 + (size_t)esrc*64))[lane];
            accv = f2fma(wP, vv, accv);
            u64t ev = ldcs1((const u64t*)(ef + (size_t)eeid*64) + lane);
            ag = f2fma(wP, ev, ag);
        }
        __syncwarp();
    }

    ((u64t*)gsm)[lane] = ag;
    __syncwarp();

    float2 og = make_float2(0.f,0.f);
    const float* Wc = We2 + lane*2;
    #pragma unroll 8
    for (int d = 0; d < 64; d++) {
        float g = gsm[d];
        float2 wr = *(const float2*)(Wc + (size_t)d*64);
        og.x += g*wr.x; og.y += g*wr.y;
    }
    float inv = (den > 0.f) ? (1.f/den) : 0.f;
    float2 av; upk(accv, av.x, av.y);
    float2 s2 = *(const float2*)(g_s2 + (size_t)n*64 + lane*2);
    float2 o;
    o.x = fmaf(av.x + og.x, inv, s2.x);
    o.y = fmaf(av.y + og.y, inv, s2.y);
    *(float2*)(out + (size_t)n*64 + lane*2) = o;
}

// ---------------- launch -------------------------------------------------------
extern "C" void kernel_launch(void* const* d_in, const int* in_sizes, int n_in,
                              void* d_out, int out_size)
{
    const float* x   = (const float*)d_in[0];
    const float* ef  = (const float*)d_in[1];
    const int*   ei  = (const int*)  d_in[2];
    const float *Wq1 = (const float*)d_in[3],  *bq1 = (const float*)d_in[4];
    const float *Wk1 = (const float*)d_in[5],  *bk1 = (const float*)d_in[6];
    const float *Wv1 = (const float*)d_in[7],  *bv1 = (const float*)d_in[8];
    const float *We1 = (const float*)d_in[9];
    const float *Ws1 = (const float*)d_in[10], *bs1 = (const float*)d_in[11];
    const float *Wq2 = (const float*)d_in[12], *bq2 = (const float*)d_in[13];
    const float *Wk2 = (const float*)d_in[14], *bk2 = (const float*)d_in[15];
    const float *Wv2 = (const float*)d_in[16], *bv2 = (const float*)d_in[17];
    const float *We2 = (const float*)d_in[18];
    const float *Ws2 = (const float*)d_in[19], *bs2 = (const float*)d_in[20];
    float* out = (float*)d_out;

    const int* srcp = ei;
    const int* dstp = ei + EE;

    // CSR build
    k_zero_cnt<<<(NN+255)/256, 256>>>();
    k_hist    <<<(EE+255)/256, 256>>>(dstp);
    k_scanA   <<<49, 1024>>>();
    k_scanB   <<<1, 64>>>();
    k_scanC   <<<(NN+255)/256, 256>>>();
    k_scatter <<<(EE+255)/256, 256>>>(srcp, dstp);

    // layer 1
    dim3 g1((NN+63)/64, 4);
    k_node1 <<<g1, 256>>>(x, Wq1,bq1, Wk1,bk1, Wv1,bv1, Ws1,bs1);
    dim3 gt1((NN+31)/32, 4);
    k_t1    <<<gt1, 256>>>(We1);
    k_score1<<<EE/32, 128>>>(ef);
    k_agg1  <<<(NN+7)/8, 256>>>(ef, We1);

    // layer 2
    dim3 g2((NN+63)/64, 4);
    k_node2 <<<g2, 256>>>(Wq2,bq2, Wk2,bk2, Wv2,bv2, Ws2,bs2);
    k_t2    <<<(NN+31)/32, 256>>>(We2);
    k_score2<<<EE/32, 128>>>(ef);
    k_agg2  <<<(NN+7)/8, 256>>>(ef, We2, out);
}

// round 14
// speedup vs baseline: 1.1431x; 1.0748x over previous
#include <cuda_runtime.h>
#include <cuda_bf16.h>

#define NN 50000
#define EE 1600000
#define FULL 0xffffffffu

typedef unsigned long long u64t;
typedef unsigned int u32;

__device__ __forceinline__ u64t pk(float lo, float hi) {
    u64t r; asm("mov.b64 %0,{%1,%2};" : "=l"(r) : "f"(lo), "f"(hi)); return r;
}
__device__ __forceinline__ void upk(u64t v, float& lo, float& hi) {
    asm("mov.b64 {%0,%1},%2;" : "=f"(lo), "=f"(hi) : "l"(v));
}
__device__ __forceinline__ u64t f2fma(u64t a, u64t b, u64t c) {
    u64t d; asm("fma.rn.f32x2 %0,%1,%2,%3;" : "=l"(d) : "l"(a), "l"(b), "l"(c)); return d;
}
__device__ __forceinline__ u64t ldcs1(const u64t* p) {
    u64t r; asm("ld.global.cs.u64 %0,[%1];" : "=l"(r) : "l"(p)); return r;
}
__device__ __forceinline__ float4 ldcs4f(const float4* p) {
    float4 r;
    asm("ld.global.cs.v4.f32 {%0,%1,%2,%3},[%4];"
        : "=f"(r.x), "=f"(r.y), "=f"(r.z), "=f"(r.w) : "l"(p));
    return r;
}
// bf16x2 packed fma (elementwise; accumulate in bf16x2)
__device__ __forceinline__ u32 bffma2(u32 a, u32 b, u32 c) {
    u32 d; asm("fma.rn.bf16x2 %0,%1,%2,%3;" : "=r"(d) : "r"(a), "r"(b), "r"(c)); return d;
}
// sum of the two bf16 halves, as float
__device__ __forceinline__ float bfsum2(u32 v) {
    float lo = __uint_as_float(v << 16);
    float hi = __uint_as_float(v & 0xffff0000u);
    return lo + hi;
}
// pack two floats into bf16x2 {lo, hi}
__device__ __forceinline__ u32 f2bf2(float lo, float hi) {
    u32 r; asm("cvt.rn.bf16x2.f32 %0,%1,%2;" : "=r"(r) : "f"(hi), "f"(lo)); return r;
}

// ---------------- scratch ----------------------------------------------------
__device__ __nv_bfloat16 g_q1b[NN*128];   // pre-scaled by 1/sqrt(32)
__device__ __nv_bfloat16 g_k1b[NN*128];
__device__ __nv_bfloat16 g_t1b[NN*256];   // from pre-scaled q -> pre-scaled
__device__ __nv_bfloat16 g_q2b[NN*64];    // pre-scaled by 0.125
__device__ __nv_bfloat16 g_k2b[NN*64];
__device__ __nv_bfloat16 g_t2b[NN*64];
__device__ float g_v1[NN*128];
__device__ float g_h [NN*128];
__device__ float g_v2[NN*64];
__device__ float g_s2[NN*64];
__device__ float g_w [EE*4];
__device__ int   g_cnt[NN];
__device__ int   g_rowptr[NN+1];
__device__ int   g_woff[NN];
__device__ int   g_bsum[64];
__device__ int2  g_edges[EE];
__device__ int   g_edst[EE];

// ---------------- CSR build ---------------------------------------------------
__global__ void k_zero_cnt() {
    int i = blockIdx.x*blockDim.x + threadIdx.x;
    if (i < NN) g_cnt[i] = 0;
}
__global__ void k_hist(const int* __restrict__ dst) {
    int e = blockIdx.x*blockDim.x + threadIdx.x;
    if (e < EE) atomicAdd(&g_cnt[dst[e]], 1);
}
__global__ void k_scanA() {
    __shared__ int s[1024];
    int b = blockIdx.x;
    int i = b*1024 + threadIdx.x;
    int v = (i < NN) ? g_cnt[i] : 0;
    s[threadIdx.x] = v;
    __syncthreads();
    for (int off = 1; off < 1024; off <<= 1) {
        int t = (threadIdx.x >= off) ? s[threadIdx.x - off] : 0;
        __syncthreads();
        s[threadIdx.x] += t;
        __syncthreads();
    }
    if (i < NN) g_rowptr[i] = s[threadIdx.x] - v;
    if (threadIdx.x == 1023) g_bsum[b] = s[1023];
}
__global__ void k_scanB() {
    __shared__ int s[64];
    int t = threadIdx.x;
    int v = (t < 49) ? g_bsum[t] : 0;
    s[t] = v;
    __syncthreads();
    for (int off = 1; off < 64; off <<= 1) {
        int x = (t >= off) ? s[t - off] : 0;
        __syncthreads();
        s[t] += x;
        __syncthreads();
    }
    if (t < 49) g_bsum[t] = s[t] - v;
    if (t == 48) g_rowptr[NN] = s[48];
}
__global__ void k_scanC() {
    int i = blockIdx.x*blockDim.x + threadIdx.x;
    if (i < NN) {
        int r = g_rowptr[i] + g_bsum[i >> 10];
        g_rowptr[i] = r;
        g_woff[i] = r;
    }
}
__global__ void k_scatter(const int* __restrict__ src, const int* __restrict__ dst) {
    int e = blockIdx.x*blockDim.x + threadIdx.x;
    if (e < EE) {
        int d = dst[e];
        int p = atomicAdd(&g_woff[d], 1);
        g_edges[p] = make_int2(src[e], e);
        g_edst[p] = d;
    }
}

// ---------------- node linear layer 1 ------------------------------------------
// mats 0,1 (q,k) -> bf16 (q pre-scaled); mats 2,3 (v, skip) -> fp32
__global__ void __launch_bounds__(256) k_node1(const float* __restrict__ x,
    const float* __restrict__ Wq, const float* __restrict__ bq,
    const float* __restrict__ Wk, const float* __restrict__ bk,
    const float* __restrict__ Wv, const float* __restrict__ bv,
    const float* __restrict__ Ws, const float* __restrict__ bs)
{
    const int CIN = 128, COUT = 128, BN = 64, KC = 16;
    int mat = blockIdx.y;
    const float* W = (mat==0)?Wq:((mat==1)?Wk:((mat==2)?Wv:Ws));
    const float* b = (mat==0)?bq:((mat==1)?bk:((mat==2)?bv:bs));
    int n0 = blockIdx.x * BN;
    int tid = threadIdx.x;
    int lane = tid & 31, ty = tid >> 5;

    __shared__ float xs[CIN][BN];
    __shared__ float ws2[KC][2*COUT];

    for (int i = tid; i < BN*CIN; i += 256) {
        int nn = i >> 7, c = i & 127;
        xs[c][nn] = (n0+nn < NN) ? x[(size_t)(n0+nn)*CIN + c] : 0.f;
    }

    u64t acc[4][4];
    #pragma unroll
    for (int c = 0; c < 4; c++) {
        float bc = b[lane + 32*c];
        u64t bp = pk(bc, bc);
        acc[0][c] = bp; acc[1][c] = bp; acc[2][c] = bp; acc[3][c] = bp;
    }

    for (int kc = 0; kc < CIN; kc += KC) {
        __syncthreads();
        for (int i = tid; i < KC*COUT; i += 256) {
            int kk = i >> 7, c = i & 127;
            float w = W[(size_t)(kc+kk)*COUT + c];
            *(float2*)&ws2[kk][2*c] = make_float2(w, w);
        }
        __syncthreads();
        #pragma unroll 4
        for (int kk = 0; kk < KC; kk++) {
            const u64t* xr = (const u64t*)&xs[kc+kk][ty*8];
            u64t x0 = xr[0], x1 = xr[1], x2 = xr[2], x3 = xr[3];
            const u64t* wr = (const u64t*)ws2[kk];
            u64t w0 = wr[lane], w1 = wr[lane+32], w2 = wr[lane+64], w3 = wr[lane+96];
            acc[0][0]=f2fma(x0,w0,acc[0][0]); acc[0][1]=f2fma(x0,w1,acc[0][1]);
            acc[0][2]=f2fma(x0,w2,acc[0][2]); acc[0][3]=f2fma(x0,w3,acc[0][3]);
            acc[1][0]=f2fma(x1,w0,acc[1][0]); acc[1][1]=f2fma(x1,w1,acc[1][1]);
            acc[1][2]=f2fma(x1,w2,acc[1][2]); acc[1][3]=f2fma(x1,w3,acc[1][3]);
            acc[2][0]=f2fma(x2,w0,acc[2][0]); acc[2][1]=f2fma(x2,w1,acc[2][1]);
            acc[2][2]=f2fma(x2,w2,acc[2][2]); acc[2][3]=f2fma(x2,w3,acc[2][3]);
            acc[3][0]=f2fma(x3,w0,acc[3][0]); acc[3][1]=f2fma(x3,w1,acc[3][1]);
            acc[3][2]=f2fma(x3,w2,acc[3][2]); acc[3][3]=f2fma(x3,w3,acc[3][3]);
        }
    }
    if (mat < 2) {
        __nv_bfloat16* ob = (mat==0) ? g_q1b : g_k1b;
        float sc = (mat==0) ? 0.1767766952966369f : 1.f;
        #pragma unroll
        for (int j = 0; j < 4; j++) {
            int r0 = n0 + ty*8 + 2*j, r1 = r0 + 1;
            #pragma unroll
            for (int c = 0; c < 4; c++) {
                float a0, a1; upk(acc[j][c], a0, a1);
                if (r0 < NN) ob[(size_t)r0*COUT + lane + 32*c] = __float2bfloat16(a0*sc);
                if (r1 < NN) ob[(size_t)r1*COUT + lane + 32*c] = __float2bfloat16(a1*sc);
            }
        }
    } else {
        float* o = (mat==2) ? g_v1 : g_h;
        #pragma unroll
        for (int j = 0; j < 4; j++) {
            int r0 = n0 + ty*8 + 2*j, r1 = r0 + 1;
            #pragma unroll
            for (int c = 0; c < 4; c++) {
                float a0, a1; upk(acc[j][c], a0, a1);
                if (r0 < NN) o[(size_t)r0*COUT + lane + 32*c] = a0;
                if (r1 < NN) o[(size_t)r1*COUT + lane + 32*c] = a1;
            }
        }
    }
}

__global__ void __launch_bounds__(256) k_node2(
    const float* __restrict__ Wq, const float* __restrict__ bq,
    const float* __restrict__ Wk, const float* __restrict__ bk,
    const float* __restrict__ Wv, const float* __restrict__ bv,
    const float* __restrict__ Ws, const float* __restrict__ bs)
{
    const int CIN = 128, COUT = 64, BN = 64, KC = 16;
    int mat = blockIdx.y;
    const float* W = (mat==0)?Wq:((mat==1)?Wk:((mat==2)?Wv:Ws));
    const float* b = (mat==0)?bq:((mat==1)?bk:((mat==2)?bv:bs));
    int n0 = blockIdx.x * BN;
    int tid = threadIdx.x;
    int lane = tid & 31, ty = tid >> 5;

    __shared__ float xs[CIN][BN];
    __shared__ float ws2[KC][2*COUT];

    for (int i = tid; i < BN*CIN; i += 256) {
        int nn = i >> 7, c = i & 127;
        xs[c][nn] = (n0+nn < NN) ? g_h[(size_t)(n0+nn)*CIN + c] : 0.f;
    }

    u64t acc[4][2];
    #pragma unroll
    for (int c = 0; c < 2; c++) {
        float bc = b[lane + 32*c];
        u64t bp = pk(bc, bc);
        acc[0][c] = bp; acc[1][c] = bp; acc[2][c] = bp; acc[3][c] = bp;
    }

    for (int kc = 0; kc < CIN; kc += KC) {
        __syncthreads();
        for (int i = tid; i < KC*COUT; i += 256) {
            int kk = i >> 6, c = i & 63;
            float w = W[(size_t)(kc+kk)*COUT + c];
            *(float2*)&ws2[kk][2*c] = make_float2(w, w);
        }
        __syncthreads();
        #pragma unroll 4
        for (int kk = 0; kk < KC; kk++) {
            const u64t* xr = (const u64t*)&xs[kc+kk][ty*8];
            u64t x0 = xr[0], x1 = xr[1], x2 = xr[2], x3 = xr[3];
            const u64t* wr = (const u64t*)ws2[kk];
            u64t w0 = wr[lane], w1 = wr[lane+32];
            acc[0][0]=f2fma(x0,w0,acc[0][0]); acc[0][1]=f2fma(x0,w1,acc[0][1]);
            acc[1][0]=f2fma(x1,w0,acc[1][0]); acc[1][1]=f2fma(x1,w1,acc[1][1]);
            acc[2][0]=f2fma(x2,w0,acc[2][0]); acc[2][1]=f2fma(x2,w1,acc[2][1]);
            acc[3][0]=f2fma(x3,w0,acc[3][0]); acc[3][1]=f2fma(x3,w1,acc[3][1]);
        }
    }
    if (mat < 2) {
        __nv_bfloat16* ob = (mat==0) ? g_q2b : g_k2b;
        float sc = (mat==0) ? 0.125f : 1.f;
        #pragma unroll
        for (int j = 0; j < 4; j++) {
            int r0 = n0 + ty*8 + 2*j, r1 = r0 + 1;
            #pragma unroll
            for (int c = 0; c < 2; c++) {
                float a0, a1; upk(acc[j][c], a0, a1);
                if (r0 < NN) ob[(size_t)r0*COUT + lane + 32*c] = __float2bfloat16(a0*sc);
                if (r1 < NN) ob[(size_t)r1*COUT + lane + 32*c] = __float2bfloat16(a1*sc);
            }
        }
    } else {
        float* o = (mat==2) ? g_v2 : g_s2;
        #pragma unroll
        for (int j = 0; j < 4; j++) {
            int r0 = n0 + ty*8 + 2*j, r1 = r0 + 1;
            #pragma unroll
            for (int c = 0; c < 2; c++) {
                float a0, a1; upk(acc[j][c], a0, a1);
                if (r0 < NN) o[(size_t)r0*COUT + lane + 32*c] = a0;
                if (r1 < NN) o[(size_t)r1*COUT + lane + 32*c] = a1;
            }
        }
    }
}

// ---------------- t tables (bf16 in/out; q pre-scaled -> t pre-scaled) -------
__global__ void k_t1(const float* __restrict__ We1) {
    int h = blockIdx.y;
    __shared__ float Wt[32][65];
    __shared__ float qsm[32][33];
    int tid = threadIdx.x;
    for (int i = tid; i < 64*32; i += 256) {
        int d = i >> 5, c = i & 31;
        Wt[c][d] = We1[(size_t)d*128 + h*32 + c];
    }
    int n0 = blockIdx.x * 32;
    for (int i = tid; i < 32*32; i += 256) {
        int nn = i >> 5, c = i & 31;
        qsm[nn][c] = (n0+nn < NN)
            ? __bfloat162float(g_q1b[(size_t)(n0+nn)*128 + h*32 + c]) : 0.f;
    }
    __syncthreads();
    int d = tid & 63, nb = tid >> 6;
    #pragma unroll
    for (int p = 0; p < 8; p++) {
        int nn = p*4 + nb;
        float acc = 0.f;
        #pragma unroll
        for (int c = 0; c < 32; c++) acc += qsm[nn][c] * Wt[c][d];
        if (n0+nn < NN) g_t1b[(size_t)(n0+nn)*256 + h*64 + d] = __float2bfloat16(acc);
    }
}

__global__ void k_t2(const float* __restrict__ We2) {
    __shared__ float Wt[64][65];
    __shared__ float qsm[32][65];
    int tid = threadIdx.x;
    for (int i = tid; i < 64*64; i += 256) {
        int d = i >> 6, c = i & 63;
        Wt[c][d] = We2[(size_t)d*64 + c];
    }
    int n0 = blockIdx.x * 32;
    for (int i = tid; i < 32*64; i += 256) {
        int nn = i >> 6, c = i & 63;
        qsm[nn][c] = (n0+nn < NN)
            ? __bfloat162float(g_q2b[(size_t)(n0+nn)*64 + c]) : 0.f;
    }
    __syncthreads();
    int d = tid & 63, nb = tid >> 6;
    #pragma unroll
    for (int p = 0; p < 8; p++) {
        int nn = p*4 + nb;
        float acc = 0.f;
        #pragma unroll
        for (int c = 0; c < 64; c++) acc += qsm[nn][c] * Wt[c][d];
        if (n0+nn < NN) g_t2b[(size_t)(n0+nn)*64 + d] = __float2bfloat16(acc);
    }
}

// ---------------- layer-1 scores: edge-parallel, bf16 dot --------------------
__global__ void __launch_bounds__(256) k_score1(const float* __restrict__ ef) {
    int tid  = threadIdx.x;
    int lane = tid & 31;
    int l8   = lane & 7;
    int i    = blockIdx.x*32 + (tid >> 3);   // EE % 32 == 0
    if (i >= EE) return;

    int2 se = g_edges[i];
    int  dn = g_edst[i];
    const uint2* kp = (const uint2*)(g_k1b + (size_t)se.x*128);  // 32 uint2/row
    const uint2* qp = (const uint2*)(g_q1b + (size_t)dn*128);
    const uint4* tp = (const uint4*)(g_t1b + (size_t)dn*256);    // 32 uint4/row
    const float4* ep = (const float4*)(ef + (size_t)se.y*64);

    // ef chunk (8 floats) -> 4 bf16x2 (streaming loads)
    float4 f0 = ldcs4f(ep + l8*2), f1 = ldcs4f(ep + l8*2 + 1);
    u32 e01 = f2bf2(f0.x, f0.y), e23 = f2bf2(f0.z, f0.w);
    u32 e45 = f2bf2(f1.x, f1.y), e67 = f2bf2(f1.z, f1.w);

    float s[4];
    #pragma unroll
    for (int h = 0; h < 4; h++) {
        uint2 kv = kp[h*8 + l8];
        uint2 qv = qp[h*8 + l8];
        u32 a = bffma2(kv.x, qv.x, 0u);
        a = bffma2(kv.y, qv.y, a);
        uint4 tv = tp[h*8 + l8];
        a = bffma2(e01, tv.x, a);
        a = bffma2(e23, tv.y, a);
        a = bffma2(e45, tv.z, a);
        a = bffma2(e67, tv.w, a);
        s[h] = bfsum2(a);
    }
    #pragma unroll
    for (int o = 1; o <= 4; o <<= 1) {
        s[0] += __shfl_xor_sync(FULL, s[0], o);
        s[1] += __shfl_xor_sync(FULL, s[1], o);
        s[2] += __shfl_xor_sync(FULL, s[2], o);
        s[3] += __shfl_xor_sync(FULL, s[3], o);
    }
    if (l8 == 0) {
        float4 w4;   // scale already folded into q/t
        w4.x = __expf(s[0]); w4.y = __expf(s[1]);
        w4.z = __expf(s[2]); w4.w = __expf(s[3]);
        *(float4*)(g_w + (size_t)i*4) = w4;
    }
}

// ---------------- layer-1 aggregate (fp32, unchanged R8) ----------------------
__global__ void __launch_bounds__(256) k_agg1(const float* __restrict__ ef,
                                              const float* __restrict__ We1) {
    int lane = threadIdx.x & 31;
    int wl   = threadIdx.x >> 5;
    int n    = blockIdx.x*8 + wl;
    __shared__ float smemAll[8*384];
    float* aux = smemAll + wl*384;
    float* gsm = aux + 128;
    if (n >= NN) return;

    int l8 = lane & 7, grp = lane >> 3;
    u64t accv0 = 0ull, accv1 = 0ull;
    u64t ag[4] = {0ull,0ull,0ull,0ull};
    float den = 0.f;

    int rs = g_rowptr[n], re = g_rowptr[n+1];
    for (int base = rs; base < re; base += 32) {
        int cnt = min(32, re - base);
        int2 se = make_int2(0, 0);
        if (lane < cnt) {
            se = g_edges[base + lane];
            *(float4*)(aux + lane*4) = *(const float4*)(g_w + (size_t)(base+lane)*4);
        }
        __syncwarp();
        #pragma unroll 2
        for (int e = 0; e < cnt; e++) {
            int esrc = __shfl_sync(FULL, se.x, e);
            int eeid = __shfl_sync(FULL, se.y, e);
            const float* we = aux + e*4;
            float w0 = we[0], w1 = we[1], w2 = we[2], w3 = we[3];
            float wg = (grp==0)?w0:((grp==1)?w1:((grp==2)?w2:w3));
            den += wg;
            u64t wgP = pk(wg, wg);
            ulonglong2 vv = ((const ulonglong2*)(g_v1 + (size_t)esrc*128))[lane];
            accv0 = f2fma(wgP, vv.x, accv0);
            accv1 = f2fma(wgP, vv.y, accv1);
            u64t ev = ldcs1((const u64t*)(ef + (size_t)eeid*64) + lane);
            ag[0] = f2fma(pk(w0,w0), ev, ag[0]);
            ag[1] = f2fma(pk(w1,w1), ev, ag[1]);
            ag[2] = f2fma(pk(w2,w2), ev, ag[2]);
            ag[3] = f2fma(pk(w3,w3), ev, ag[3]);
        }
        __syncwarp();
    }

    u64t* gU = (u64t*)gsm;
    gU[0*32 + lane] = ag[0];
    gU[1*32 + lane] = ag[1];
    gU[2*32 + lane] = ag[2];
    gU[3*32 + lane] = ag[3];
    __syncwarp();

    float4 og = make_float4(0.f,0.f,0.f,0.f);
    const float* Wc = We1 + grp*32 + l8*4;
    const float* gh = gsm + grp*64;
    #pragma unroll 8
    for (int d = 0; d < 64; d++) {
        float g = gh[d];
        float4 wr = *(const float4*)(Wc + (size_t)d*128);
        og.x += g*wr.x; og.y += g*wr.y; og.z += g*wr.z; og.w += g*wr.w;
    }
    float inv = (den > 0.f) ? (1.f/den) : 0.f;
    float4 av; upk(accv0, av.x, av.y); upk(accv1, av.z, av.w);
    float4 skip = *(const float4*)(g_h + (size_t)n*128 + lane*4);
    float4 o;
    o.x = fmaxf(fmaf(av.x + og.x, inv, skip.x), 0.f);
    o.y = fmaxf(fmaf(av.y + og.y, inv, skip.y), 0.f);
    o.z = fmaxf(fmaf(av.z + og.z, inv, skip.z), 0.f);
    o.w = fmaxf(fmaf(av.w + og.w, inv, skip.w), 0.f);
    *(float4*)(g_h + (size_t)n*128 + lane*4) = o;
}

// ---------------- layer-2 scores: edge-parallel, bf16 dot ---------------------
__global__ void __launch_bounds__(256) k_score2(const float* __restrict__ ef) {
    int tid  = threadIdx.x;
    int lane = tid & 31;
    int l8   = lane & 7;
    int i    = blockIdx.x*32 + (tid >> 3);
    if (i >= EE) return;

    int2 se = g_edges[i];
    int  dn = g_edst[i];
    const uint4* kp = (const uint4*)(g_k2b + (size_t)se.x*64);  // 8 uint4/row
    const uint4* qp = (const uint4*)(g_q2b + (size_t)dn*64);
    const uint4* tp = (const uint4*)(g_t2b + (size_t)dn*64);
    const float4* ep = (const float4*)(ef + (size_t)se.y*64);

    float4 f0 = ldcs4f(ep + l8*2), f1 = ldcs4f(ep + l8*2 + 1);
    u32 e01 = f2bf2(f0.x, f0.y), e23 = f2bf2(f0.z, f0.w);
    u32 e45 = f2bf2(f1.x, f1.y), e67 = f2bf2(f1.z, f1.w);

    uint4 kv = kp[l8], qv = qp[l8], tv = tp[l8];
    u32 a = bffma2(kv.x, qv.x, 0u);
    a = bffma2(kv.y, qv.y, a);
    a = bffma2(kv.z, qv.z, a);
    a = bffma2(kv.w, qv.w, a);
    a = bffma2(e01, tv.x, a);
    a = bffma2(e23, tv.y, a);
    a = bffma2(e45, tv.z, a);
    a = bffma2(e67, tv.w, a);
    float s = bfsum2(a);
    s += __shfl_xor_sync(FULL, s, 1);
    s += __shfl_xor_sync(FULL, s, 2);
    s += __shfl_xor_sync(FULL, s, 4);
    if (l8 == 0) g_w[i] = __expf(s);
}

// ---------------- layer-2 aggregate (fp32, unchanged R8) ----------------------
__global__ void __launch_bounds__(256) k_agg2(const float* __restrict__ ef,
                                              const float* __restrict__ We2,
                                              float* __restrict__ out) {
    int lane = threadIdx.x & 31;
    int wl   = threadIdx.x >> 5;
    int n    = blockIdx.x*8 + wl;
    __shared__ float smemAll[8*96];
    float* aux = smemAll + wl*96;
    float* gsm = aux + 32;
    if (n >= NN) return;

    u64t accv = 0ull;
    u64t ag   = 0ull;
    float den = 0.f;
    int rs = g_rowptr[n], re = g_rowptr[n+1];

    for (int base = rs; base < re; base += 32) {
        int cnt = min(32, re - base);
        int2 se = make_int2(0, 0);
        if (lane < cnt) {
            se = g_edges[base + lane];
            aux[lane] = g_w[base + lane];
        }
        __syncwarp();
        #pragma unroll 2
        for (int e = 0; e < cnt; e++) {
            int esrc = __shfl_sync(FULL, se.x, e);
            int eeid = __shfl_sync(FULL, se.y, e);
            float w = aux[e];
            den += w;
            u64t wP = pk(w, w);
            u64t vv = ((const u64t*)(g_v2 + (size_t)esrc*64))[lane];
            accv = f2fma(wP, vv, accv);
            u64t ev = ldcs1((const u64t*)(ef + (size_t)eeid*64) + lane);
            ag = f2fma(wP, ev, ag);
        }
        __syncwarp();
    }

    ((u64t*)gsm)[lane] = ag;
    __syncwarp();

    float2 og = make_float2(0.f,0.f);
    const float* Wc = We2 + lane*2;
    #pragma unroll 8
    for (int d = 0; d < 64; d++) {
        float g = gsm[d];
        float2 wr = *(const float2*)(Wc + (size_t)d*64);
        og.x += g*wr.x; og.y += g*wr.y;
    }
    float inv = (den > 0.f) ? (1.f/den) : 0.f;
    float2 av; upk(accv, av.x, av.y);
    float2 s2 = *(const float2*)(g_s2 + (size_t)n*64 + lane*2);
    float2 o;
    o.x = fmaf(av.x + og.x, inv, s2.x);
    o.y = fmaf(av.y + og.y, inv, s2.y);
    *(float2*)(out + (size_t)n*64 + lane*2) = o;
}

// ---------------- launch -------------------------------------------------------
extern "C" void kernel_launch(void* const* d_in, const int* in_sizes, int n_in,
                              void* d_out, int out_size)
{
    const float* x   = (const float*)d_in[0];
    const float* ef  = (const float*)d_in[1];
    const int*   ei  = (const int*)  d_in[2];
    const float *Wq1 = (const float*)d_in[3],  *bq1 = (const float*)d_in[4];
    const float *Wk1 = (const float*)d_in[5],  *bk1 = (const float*)d_in[6];
    const float *Wv1 = (const float*)d_in[7],  *bv1 = (const float*)d_in[8];
    const float *We1 = (const float*)d_in[9];
    const float *Ws1 = (const float*)d_in[10], *bs1 = (const float*)d_in[11];
    const float *Wq2 = (const float*)d_in[12], *bq2 = (const float*)d_in[13];
    const float *Wk2 = (const float*)d_in[14], *bk2 = (const float*)d_in[15];
    const float *Wv2 = (const float*)d_in[16], *bv2 = (const float*)d_in[17];
    const float *We2 = (const float*)d_in[18];
    const float *Ws2 = (const float*)d_in[19], *bs2 = (const float*)d_in[20];
    float* out = (float*)d_out;

    const int* srcp = ei;
    const int* dstp = ei + EE;

    // CSR build
    k_zero_cnt<<<(NN+255)/256, 256>>>();
    k_hist    <<<(EE+255)/256, 256>>>(dstp);
    k_scanA   <<<49, 1024>>>();
    k_scanB   <<<1, 64>>>();
    k_scanC   <<<(NN+255)/256, 256>>>();
    k_scatter <<<(EE+255)/256, 256>>>(srcp, dstp);

    // layer 1
    dim3 g1((NN+63)/64, 4);
    k_node1 <<<g1, 256>>>(x, Wq1,bq1, Wk1,bk1, Wv1,bv1, Ws1,bs1);
    dim3 gt1((NN+31)/32, 4);
    k_t1    <<<gt1, 256>>>(We1);
    k_score1<<<EE/32, 256>>>(ef);
    k_agg1  <<<(NN+7)/8, 256>>>(ef, We1);

    // layer 2
    dim3 g2((NN+63)/64, 4);
    k_node2 <<<g2, 256>>>(Wq2,bq2, Wk2,bk2, Wv2,bv2, Ws2,bs2);
    k_t2    <<<(NN+31)/32, 256>>>(We2);
    k_score2<<<EE/32, 256>>>(ef);
    k_agg2  <<<(NN+7)/8, 256>>>(ef, We2, out);
}